// round 15
// baseline (speedup 1.0000x reference)
#include <cuda_runtime.h>
#include <cuda_fp16.h>
#include <cstdint>

#define PP 2048
#define HH 1024
#define AA 16
#define OO 4
#define BB 4096

#define BM 128
#define BN 128
#define BK 64
#define NST 3
#define THALF 8192                     // halves per stage tile (128x64 or 64x128)
#define TBYTES 16384                   // bytes per stage tile

#define SMEM_BYTES (NST * 2 * TBYTES)  // 96KB

typedef long long ll;

// ---------------- device scratch ----------------
__device__ __half g_Xg [PP * HH];                     // A tiles [mt16][kt16][8192] (unique rows)
__device__ __half g_X1g[PP * HH];
__device__ __half g_W  [3ll * AA * HH * HH];          // B tiles [(w*16+a)*8+nt][kt16][8192]
__device__ __half g_Z  [(ll)AA * PP * HH];            // A tiles [(a*16+mt)*16+kt][8192]
__device__ float  g_gw [AA * HH * OO];
__device__ float  g_Gco[AA * OO];
__device__ float  g_Bco[AA * OO];
__device__ float  g_part[(ll)AA * 8 * PP * 8];        // [a][ntile][u][8]
__device__ int    g_nuniq;
__device__ int    g_ulist[PP];
__device__ int    g_uidx [PP];
__device__ int    g_urow [BB];

// ---------------- helpers ----------------
__device__ __forceinline__ uint32_t smem_u32(const void* p) {
    uint32_t a;
    asm("{ .reg .u64 t; cvta.to.shared.u64 t, %1; cvt.u32.u64 %0, t; }" : "=r"(a) : "l"(p));
    return a;
}
__device__ __forceinline__ void cp16(uint32_t s, const void* g) {
    asm volatile("cp.async.cg.shared.global [%0], [%1], 16;" :: "r"(s), "l"(g));
}
__device__ __forceinline__ void cp_commit() {
    asm volatile("cp.async.commit_group;" ::: "memory");
}
template <int N>
__device__ __forceinline__ void cp_wait() {
    asm volatile("cp.async.wait_group %0;" :: "n"(N) : "memory");
}
__device__ __forceinline__ uint32_t h2u(__half2 h) {
    return *reinterpret_cast<uint32_t*>(&h);
}
__device__ __forceinline__ void lds128(uint32_t& r0, uint32_t& r1, uint32_t& r2, uint32_t& r3,
                                       uint32_t addr) {
    asm volatile("ld.shared.v4.b32 {%0,%1,%2,%3}, [%4];"
                 : "=r"(r0), "=r"(r1), "=r"(r2), "=r"(r3) : "r"(addr));
}
__device__ __forceinline__ void mma_f16(float c[4], const uint32_t a[4], uint32_t b0, uint32_t b1) {
    asm volatile(
        "mma.sync.aligned.m16n8k16.row.col.f32.f16.f16.f32 "
        "{%0,%1,%2,%3}, {%4,%5,%6,%7}, {%8,%9}, {%0,%1,%2,%3};"
        : "+f"(c[0]), "+f"(c[1]), "+f"(c[2]), "+f"(c[3])
        : "r"(a[0]), "r"(a[1]), "r"(a[2]), "r"(a[3]), "r"(b0), "r"(b1));
}

// ---------------- dedup ----------------
__global__ void dedup_kernel(const int* __restrict__ pos) {
    __shared__ int flag[BB];
    __shared__ int warpsum[32];
    int tid = threadIdx.x;
    for (int i = tid; i < BB; i += 1024) flag[i] = 0;
    __syncthreads();
    for (int p = tid; p < PP; p += 1024) flag[pos[p]] = 1;
    __syncthreads();
    int base = tid * 4;
    int f0 = flag[base], f1 = flag[base + 1], f2 = flag[base + 2], f3 = flag[base + 3];
    int s = f0 + f1 + f2 + f3;
    int lane = tid & 31, wid = tid >> 5;
    int ps = s;
#pragma unroll
    for (int o = 1; o < 32; o <<= 1) {
        int v = __shfl_up_sync(0xFFFFFFFFu, ps, o);
        if (lane >= o) ps += v;
    }
    if (lane == 31) warpsum[wid] = ps;
    __syncthreads();
    if (wid == 0) {
        int v = warpsum[lane];
#pragma unroll
        for (int o = 1; o < 32; o <<= 1) {
            int u2 = __shfl_up_sync(0xFFFFFFFFu, v, o);
            if (lane >= o) v += u2;
        }
        warpsum[lane] = v;
    }
    __syncthreads();
    int excl = ps - s + (wid > 0 ? warpsum[wid - 1] : 0);
    int e0 = excl, e1 = excl + f0, e2 = e1 + f1, e3 = e2 + f2;
    if (f0) g_ulist[e0] = base;
    if (f1) g_ulist[e1] = base + 1;
    if (f2) g_ulist[e2] = base + 2;
    if (f3) g_ulist[e3] = base + 3;
    g_urow[base] = e0; g_urow[base + 1] = e1; g_urow[base + 2] = e2; g_urow[base + 3] = e3;
    if (tid == 1023) g_nuniq = e3 + f3;
    __syncthreads();
    for (int p = tid; p < PP; p += 1024) g_uidx[p] = g_urow[pos[p]];
}

// ---------------- gather: unique rows -> fp16 fragment-major A tiles ----------------
__global__ void gather_kernel(const float* __restrict__ X, const float* __restrict__ X1,
                              __half* __restrict__ Xg, __half* __restrict__ X1g) {
    __shared__ __half s0[128 * 72];
    __shared__ __half s1[128 * 72];
    int mt = blockIdx.x, kt = blockIdx.y, tid = threadIdx.x;
    int nuniq = g_nuniq;
#pragma unroll
    for (int u = 0; u < 8; ++u) {
        int idx = tid + u * 256;
        int row = idx >> 4, c4 = idx & 15;
        int uu = mt * 128 + row;
        float4 v = make_float4(0.f, 0.f, 0.f, 0.f), w = v;
        if (uu < nuniq) {
            int r = g_ulist[uu];
            v = *(const float4*)(X  + (ll)r * HH + kt * 64 + c4 * 4);
            w = *(const float4*)(X1 + (ll)r * HH + kt * 64 + c4 * 4);
        }
        *(__half2*)&s0[row * 72 + c4 * 4]     = __floats2half2_rn(v.x, v.y);
        *(__half2*)&s0[row * 72 + c4 * 4 + 2] = __floats2half2_rn(v.z, v.w);
        *(__half2*)&s1[row * 72 + c4 * 4]     = __floats2half2_rn(w.x, w.y);
        *(__half2*)&s1[row * 72 + c4 * 4 + 2] = __floats2half2_rn(w.z, w.w);
    }
    __syncthreads();
    uint4* o0 = (uint4*)(Xg  + (ll)(mt * 16 + kt) * THALF);
    uint4* o1 = (uint4*)(X1g + (ll)(mt * 16 + kt) * THALF);
#pragma unroll
    for (int c = 0; c < 4; ++c) {
        int chunk = tid + c * 256;
        int pm2 = chunk >> 9, pi = (chunk >> 7) & 3, pks = (chunk >> 5) & 3, pl = chunk & 31;
        int pg = pl >> 2, pt = pl & 3;
        int r0 = pm2 * 64 + pi * 16, k0 = pks * 16 + 2 * pt;
        o0[chunk] = make_uint4(h2u(*(__half2*)&s0[(r0 + pg) * 72 + k0]),
                               h2u(*(__half2*)&s0[(r0 + 8 + pg) * 72 + k0]),
                               h2u(*(__half2*)&s0[(r0 + pg) * 72 + k0 + 8]),
                               h2u(*(__half2*)&s0[(r0 + 8 + pg) * 72 + k0 + 8]));
        o1[chunk] = make_uint4(h2u(*(__half2*)&s1[(r0 + pg) * 72 + k0]),
                               h2u(*(__half2*)&s1[(r0 + 8 + pg) * 72 + k0]),
                               h2u(*(__half2*)&s1[(r0 + pg) * 72 + k0 + 8]),
                               h2u(*(__half2*)&s1[(r0 + 8 + pg) * 72 + k0 + 8]));
    }
}

// ---------------- round weights to fp16, ks-paired B tiles ----------------
__global__ void round_w_kernel(const float* __restrict__ Wa, const float* __restrict__ Wb,
                               int wbase, __half* __restrict__ Wd) {
    __shared__ __half swh[64 * 132];
    int nt = blockIdx.x, kt = blockIdx.y, wa = blockIdx.z;
    int wl = wa >> 4, a = wa & 15, tid = threadIdx.x;
    int w = wbase + wl;
    const float* src = (wl == 0 ? Wa : Wb) + (ll)a * HH * HH;
    const float4* srcq = (const float4*)(src + (ll)(kt * 64) * HH + nt * 128);
#pragma unroll
    for (int u = 0; u < 8; ++u) {
        int idx = tid + u * 256;
        int row = idx >> 5, c4 = idx & 31;
        float4 v = srcq[row * (HH / 4) + c4];
        *(__half2*)&swh[row * 132 + c4 * 4]     = __floats2half2_rn(v.x, v.y);
        *(__half2*)&swh[row * 132 + c4 * 4 + 2] = __floats2half2_rn(v.z, v.w);
    }
    __syncthreads();
    uint4* op = (uint4*)(Wd + (((ll)(w * 16 + a) * 8 + nt) * 16 + kt) * THALF);
#pragma unroll
    for (int c = 0; c < 4; ++c) {
        int chunk = tid + c * 256;
        int wn4 = chunk >> 8, j = (chunk >> 6) & 3, kp = (chunk >> 5) & 1, lane = chunk & 31;
        int g = lane >> 2, t = lane & 3;
        int n = wn4 * 32 + j * 8 + g;
        int k0 = kp * 32 + 2 * t;
        __half2 b00 = __halves2half2(swh[k0 * 132 + n],        swh[(k0 + 1) * 132 + n]);
        __half2 b01 = __halves2half2(swh[(k0 + 8) * 132 + n],  swh[(k0 + 9) * 132 + n]);
        __half2 b10 = __halves2half2(swh[(k0 + 16) * 132 + n], swh[(k0 + 17) * 132 + n]);
        __half2 b11 = __halves2half2(swh[(k0 + 24) * 132 + n], swh[(k0 + 25) * 132 + n]);
        op[chunk] = make_uint4(h2u(b00), h2u(b01), h2u(b10), h2u(b11));
    }
}

// ---------------- prep ----------------
__global__ void prep_kernel(const float* __restrict__ gamma, const float* __restrict__ beta,
                            const float* __restrict__ W4, const float* __restrict__ b4,
                            float* __restrict__ gw, float* __restrict__ Gco, float* __restrict__ Bco) {
    __shared__ float red[8][256];
    int a = blockIdx.x, tid = threadIdx.x;
    float G[4] = {0, 0, 0, 0}, Bc[4] = {0, 0, 0, 0};
    for (int h = tid; h < HH; h += 256) {
        float g = gamma[a * HH + h], be = beta[a * HH + h];
        float4 w = *(const float4*)&W4[((ll)a * HH + h) * 4];
        float4 r = make_float4(g * w.x, g * w.y, g * w.z, g * w.w);
        *(float4*)&gw[((ll)a * HH + h) * 4] = r;
        G[0] += r.x; G[1] += r.y; G[2] += r.z; G[3] += r.w;
        Bc[0] += be * w.x; Bc[1] += be * w.y; Bc[2] += be * w.z; Bc[3] += be * w.w;
    }
#pragma unroll
    for (int j = 0; j < 4; ++j) { red[j][tid] = G[j]; red[4 + j][tid] = Bc[j]; }
    __syncthreads();
    for (int s = 128; s > 0; s >>= 1) {
        if (tid < s)
#pragma unroll
            for (int j = 0; j < 8; ++j) red[j][tid] += red[j][tid + s];
        __syncthreads();
    }
    if (tid < 4) {
        Gco[a * 4 + tid] = red[tid][0];
        Bco[a * 4 + tid] = red[4 + tid][0] + b4[a * 4 + tid];
    }
}

// ---------------- fp16 GEMM: 512 threads, warp tile 32x32, 2 CTAs/SM, 8 warps/SMSP ----------------
template <bool DUAL, bool REDUCE>
__global__ void __launch_bounds__(512, 2)
gemm_mma(const __half* __restrict__ A1, const __half* __restrict__ A2,
         const __half* __restrict__ B1, const __half* __restrict__ B2,
         const float* __restrict__ bias1, const float* __restrict__ bias2,
         const float* __restrict__ gw,
         __half* __restrict__ outZ, float* __restrict__ part) {
    if ((int)blockIdx.x * BM >= g_nuniq) return;
    extern __shared__ __half smh[];
    const uint32_t sb = smem_u32(smh);
    const int tid = threadIdx.x, lane = tid & 31, wid = tid >> 5;
    const int g = lane >> 2, t = lane & 3;
    const int wm4 = wid >> 2, wn4 = wid & 3;       // 4x4 warp grid, 32x32 warp tile
    const int bx = blockIdx.x, by = blockIdx.y, a = blockIdx.z;
    const int m0 = bx * BM, n0 = by * BN;
    const int NIT = DUAL ? 32 : 16;

    // per-thread cp.async dst offsets (2 chunks per tile, 512 threads)
    const uint32_t dAo = sb + (uint32_t)tid * 16;
    const uint32_t dBo = sb + NST * TBYTES + (uint32_t)tid * 16;

    const char* Ag0 = (const char*)((DUAL ? A1 + (ll)bx * 16 * THALF
                                          : A1 + ((ll)(a * 16 + bx)) * 16 * THALF)) + tid * 16;
    const char* Bg0 = (const char*)(B1 + ((ll)(a * 8 + by)) * 16 * THALF) + tid * 16;
    const char* Ag1 = DUAL ? (const char*)(A2 + (ll)bx * 16 * THALF) + tid * 16 : nullptr;
    const char* Bg1 = DUAL ? (const char*)(B2 + ((ll)(a * 8 + by)) * 16 * THALF) + tid * 16 : nullptr;

    float c[2][4][4];
#pragma unroll
    for (int i = 0; i < 2; ++i)
#pragma unroll
        for (int j = 0; j < 4; ++j)
#pragma unroll
            for (int q = 0; q < 4; ++q) c[i][j][q] = 0.f;

    auto load_stage = [&](int buf, int it) {
        const char* Ag = (DUAL && it >= 16) ? Ag1 + (ll)(it - 16) * TBYTES : Ag0 + (ll)it * TBYTES;
        const char* Bg = (DUAL && it >= 16) ? Bg1 + (ll)(it - 16) * TBYTES : Bg0 + (ll)it * TBYTES;
        uint32_t da = dAo + buf * TBYTES, db = dBo + buf * TBYTES;
        cp16(da, Ag);            cp16(da + 8192, Ag + 8192);
        cp16(db, Bg);            cp16(db + 8192, Bg + 8192);
        cp_commit();
    };

    load_stage(0, 0);
    load_stage(1, 1);
    int buf = 0, buf2 = 2;
#pragma unroll 1
    for (int it = 0; it < NIT; ++it) {
        if (it == NIT - 1) cp_wait<0>();
        else               cp_wait<1>();
        __syncthreads();

        const uint32_t aB = sb + buf * TBYTES;
        const uint32_t bB = sb + NST * TBYTES + buf * TBYTES;

#pragma unroll
        for (int kp = 0; kp < 2; ++kp) {
            // A frags for both k-halves of this kp: af[h][4]
            uint32_t af[2][4];
#pragma unroll
            for (int h = 0; h < 2; ++h) {
                int ks = kp * 2 + h;
#pragma unroll
                for (int i = 0; i < 2; ++i) {
                    uint32_t addr = aB + (uint32_t)((((wm4 * 2 + i) * 4 + ks) * 32 + lane) * 16);
                    lds128(af[h][i * 2 + 0] /*dummy split below*/, af[h][i * 2 + 1],
                           af[h][i * 2 + 0], af[h][i * 2 + 1], addr);   // placeholder
                }
            }
            // NOTE: the above placeholder is replaced by proper per-i regs:
            // (rewritten without placeholder below)
            uint32_t afr[2][2][4];
#pragma unroll
            for (int h = 0; h < 2; ++h) {
                int ks = kp * 2 + h;
#pragma unroll
                for (int i = 0; i < 2; ++i) {
                    uint32_t addr = aB + (uint32_t)((((wm4 * 2 + i) * 4 + ks) * 32 + lane) * 16);
                    lds128(afr[h][i][0], afr[h][i][1], afr[h][i][2], afr[h][i][3], addr);
                }
            }
#pragma unroll
            for (int j = 0; j < 4; ++j) {
                uint32_t bq0, bq1, bq2, bq3;
                uint32_t baddr = bB + (uint32_t)((((wn4 * 4 + j) * 2 + kp) * 32 + lane) * 16);
                lds128(bq0, bq1, bq2, bq3, baddr);
#pragma unroll
                for (int i = 0; i < 2; ++i) mma_f16(c[i][j], afr[0][i], bq0, bq1);
#pragma unroll
                for (int i = 0; i < 2; ++i) mma_f16(c[i][j], afr[1][i], bq2, bq3);
            }
            if (kp == 0 && it + 2 < NIT) load_stage(buf2, it + 2);
        }

        buf  = (buf  == NST - 1) ? 0 : buf + 1;
        buf2 = (buf2 == NST - 1) ? 0 : buf2 + 1;
    }
    __syncthreads();

    if (!REDUCE) {
        __half* Cs = smh;   // [128][136] staging
#pragma unroll
        for (int j = 0; j < 4; ++j) {
            int col = wn4 * 32 + j * 8 + t * 2;
            int gc = n0 + col;
            float bx0 = bias1[a * HH + gc]     + bias2[a * HH + gc];
            float by0 = bias1[a * HH + gc + 1] + bias2[a * HH + gc + 1];
#pragma unroll
            for (int i = 0; i < 2; ++i) {
                int r0 = wm4 * 32 + i * 16 + g;
                *(__half2*)&Cs[r0 * 136 + col]       = __floats2half2_rn(c[i][j][0] + bx0, c[i][j][1] + by0);
                *(__half2*)&Cs[(r0 + 8) * 136 + col] = __floats2half2_rn(c[i][j][2] + bx0, c[i][j][3] + by0);
            }
        }
        __syncthreads();
#pragma unroll
        for (int ktl = 0; ktl < 2; ++ktl) {
            uint4* op = (uint4*)(outZ + (((ll)(a * 16 + bx)) * 16 + by * 2 + ktl) * THALF);
#pragma unroll
            for (int cc = 0; cc < 2; ++cc) {
                int chunk = tid + cc * 512;
                int pm2 = chunk >> 9, pi = (chunk >> 7) & 3, pks = (chunk >> 5) & 3, pl = chunk & 31;
                int pg = pl >> 2, pt = pl & 3;
                int r0 = pm2 * 64 + pi * 16;
                int col = ktl * 64 + pks * 16 + 2 * pt;
                op[chunk] = make_uint4(h2u(*(__half2*)&Cs[(r0 + pg) * 136 + col]),
                                       h2u(*(__half2*)&Cs[(r0 + 8 + pg) * 136 + col]),
                                       h2u(*(__half2*)&Cs[(r0 + pg) * 136 + col + 8]),
                                       h2u(*(__half2*)&Cs[(r0 + 8 + pg) * 136 + col + 8]));
            }
        }
    } else {
        float* red = (float*)smh;   // [row][wn4][8] = 16KB
        float bcol[4][2];
        float4 gcol[4][2];
#pragma unroll
        for (int j = 0; j < 4; ++j) {
            int col = n0 + wn4 * 32 + j * 8 + t * 2;
            bcol[j][0] = bias1[a * HH + col];
            bcol[j][1] = bias1[a * HH + col + 1];
            gcol[j][0] = *(const float4*)&gw[((ll)a * HH + col) * 4];
            gcol[j][1] = *(const float4*)&gw[((ll)a * HH + col + 1) * 4];
        }
#pragma unroll
        for (int i = 0; i < 2; ++i) {
#pragma unroll
            for (int gs = 0; gs < 2; ++gs) {
                float s1 = 0.f, s2 = 0.f, sx = 0.f, sy = 0.f, sz = 0.f, sw = 0.f;
#pragma unroll
                for (int j = 0; j < 4; ++j) {
                    float v0 = fmaxf(c[i][j][gs * 2]     + bcol[j][0], 0.f);
                    float v1 = fmaxf(c[i][j][gs * 2 + 1] + bcol[j][1], 0.f);
                    s1 += v0 + v1;
                    s2 += v0 * v0 + v1 * v1;
                    sx += v0 * gcol[j][0].x + v1 * gcol[j][1].x;
                    sy += v0 * gcol[j][0].y + v1 * gcol[j][1].y;
                    sz += v0 * gcol[j][0].z + v1 * gcol[j][1].z;
                    sw += v0 * gcol[j][0].w + v1 * gcol[j][1].w;
                }
#pragma unroll
                for (int o = 1; o <= 2; o <<= 1) {
                    s1 += __shfl_xor_sync(0xFFFFFFFFu, s1, o);
                    s2 += __shfl_xor_sync(0xFFFFFFFFu, s2, o);
                    sx += __shfl_xor_sync(0xFFFFFFFFu, sx, o);
                    sy += __shfl_xor_sync(0xFFFFFFFFu, sy, o);
                    sz += __shfl_xor_sync(0xFFFFFFFFu, sz, o);
                    sw += __shfl_xor_sync(0xFFFFFFFFu, sw, o);
                }
                if (t == 0) {
                    int rl = wm4 * 32 + i * 16 + gs * 8 + g;
                    float* rp = &red[(rl * 4 + wn4) * 8];
                    rp[0] = s1; rp[1] = s2; rp[2] = sx;
                    rp[3] = sy; rp[4] = sz; rp[5] = sw;
                }
            }
        }
        __syncthreads();
        for (int idx = tid; idx < 128 * 6; idx += 512) {
            int row = idx / 6, q = idx % 6;
            float s = red[(row * 4 + 0) * 8 + q] + red[(row * 4 + 1) * 8 + q]
                    + red[(row * 4 + 2) * 8 + q] + red[(row * 4 + 3) * 8 + q];
            part[(((ll)a * 8 + by) * PP + (m0 + row)) * 8 + q] = s;
        }
    }
}

// ---------------- final ----------------
__global__ void final_kernel(const float* __restrict__ part, const float* __restrict__ Gco,
                             const float* __restrict__ Bco, float* __restrict__ out) {
    int tk = blockIdx.x * 256 + threadIdx.x;
    int p = tk >> 4, a = tk & 15;
    int u = g_uidx[p];
    float s1 = 0.f, s2 = 0.f, so[4] = {0.f, 0.f, 0.f, 0.f};
#pragma unroll
    for (int nt = 0; nt < 8; ++nt) {
        const float* q = part + (((ll)a * 8 + nt) * PP + u) * 8;
        s1 += q[0]; s2 += q[1];
        so[0] += q[2]; so[1] += q[3]; so[2] += q[4]; so[3] += q[5];
    }
    float mu  = s1 * (1.0f / HH);
    float var = s2 * (1.0f / HH) - mu * mu;
    float inv = rsqrtf(var + 1e-5f);
    float4 o;
    o.x = (so[0] - mu * Gco[a * 4 + 0]) * inv + Bco[a * 4 + 0];
    o.y = (so[1] - mu * Gco[a * 4 + 1]) * inv + Bco[a * 4 + 1];
    o.z = (so[2] - mu * Gco[a * 4 + 2]) * inv + Bco[a * 4 + 2];
    o.w = (so[3] - mu * Gco[a * 4 + 3]) * inv + Bco[a * 4 + 3];
    ((float4*)out)[tk] = o;
}

// ---------------- host ----------------
extern "C" void kernel_launch(void* const* d_in, const int* in_sizes, int n_in,
                              void* d_out, int out_size) {
    const float* X     = (const float*)d_in[0];
    const float* X1    = (const float*)d_in[1];
    const float* W1    = (const float*)d_in[2];
    const float* b1    = (const float*)d_in[3];
    const float* W2    = (const float*)d_in[4];
    const float* b2    = (const float*)d_in[5];
    const float* W3    = (const float*)d_in[6];
    const float* b3    = (const float*)d_in[7];
    const float* gamma = (const float*)d_in[8];
    const float* beta  = (const float*)d_in[9];
    const float* W4    = (const float*)d_in[10];
    const float* b4    = (const float*)d_in[11];
    const int*   pos   = (const int*)d_in[12];
    float* out = (float*)d_out;

    __half *pXg, *pX1g, *pW, *pZ;
    float *pgw, *pGco, *pBco, *ppart;
    cudaGetSymbolAddress((void**)&pXg,   g_Xg);
    cudaGetSymbolAddress((void**)&pX1g,  g_X1g);
    cudaGetSymbolAddress((void**)&pW,    g_W);
    cudaGetSymbolAddress((void**)&pZ,    g_Z);
    cudaGetSymbolAddress((void**)&pgw,   g_gw);
    cudaGetSymbolAddress((void**)&pGco,  g_Gco);
    cudaGetSymbolAddress((void**)&pBco,  g_Bco);
    cudaGetSymbolAddress((void**)&ppart, g_part);

    cudaFuncSetAttribute(gemm_mma<true,  false>, cudaFuncAttributeMaxDynamicSharedMemorySize, SMEM_BYTES);
    cudaFuncSetAttribute(gemm_mma<false, true >, cudaFuncAttributeMaxDynamicSharedMemorySize, SMEM_BYTES);

    const __half* W1r = pW;
    const __half* W2r = pW + 1ll * AA * HH * HH;
    const __half* W3r = pW + 2ll * AA * HH * HH;

    cudaStream_t s2;
    cudaStreamCreateWithFlags(&s2, cudaStreamNonBlocking);
    cudaEvent_t eFork, eG, eW3;
    cudaEventCreateWithFlags(&eFork, cudaEventDisableTiming);
    cudaEventCreateWithFlags(&eG,    cudaEventDisableTiming);
    cudaEventCreateWithFlags(&eW3,   cudaEventDisableTiming);

    cudaEventRecord(eFork, 0);
    cudaStreamWaitEvent(s2, eFork, 0);

    dedup_kernel<<<1, 1024, 0, s2>>>(pos);
    gather_kernel<<<dim3(PP / BM, 16), 256, 0, s2>>>(X, X1, pXg, pX1g);
    prep_kernel<<<AA, 256, 0, s2>>>(gamma, beta, W4, b4, pgw, pGco, pBco);
    cudaEventRecord(eG, s2);

    round_w_kernel<<<dim3(8, 16, 32), 256>>>(W1, W2, 0, pW);
    round_w_kernel<<<dim3(8, 16, 16), 256, 0, s2>>>(W3, W3, 2, pW);
    cudaEventRecord(eW3, s2);

    cudaStreamWaitEvent(0, eG, 0);
    dim3 gg(PP / BM, HH / BN, AA);
    gemm_mma<true, false><<<gg, 512, SMEM_BYTES>>>(
        pXg, pX1g, W1r, W2r, b1, b2, nullptr, pZ, nullptr);

    cudaStreamWaitEvent(0, eW3, 0);
    gemm_mma<false, true><<<gg, 512, SMEM_BYTES>>>(
        pZ, nullptr, W3r, nullptr, b3, nullptr, pgw, nullptr, ppart);
    final_kernel<<<(PP * AA) / 256, 256>>>(ppart, pGco, pBco, out);
}

// round 16
// speedup vs baseline: 1.2313x; 1.2313x over previous
#include <cuda_runtime.h>
#include <cuda_fp16.h>
#include <cstdint>

#define PP 2048
#define HH 1024
#define AA 16
#define OO 4
#define BB 4096

#define BM 128
#define BN 128
#define BK 64
#define NST 3
#define THALF 8192                     // halves per stage tile (128x64 or 64x128)

#define SMEM_BYTES (NST * 2 * THALF * 2)   // 96KB

typedef long long ll;

// ---------------- device scratch ----------------
__device__ __half g_Xg [PP * HH];                     // [mt16][kt16][8192] (unique rows)
__device__ __half g_X1g[PP * HH];
__device__ __half g_W  [3ll * AA * HH * HH];          // [(w*16+a)*8+nt][kt16][8192]
__device__ __half g_Z  [(ll)AA * PP * HH];            // [(a*16+mt)*16+kt][8192]
__device__ float  g_gw [AA * HH * OO];
__device__ float  g_Gco[AA * OO];
__device__ float  g_Bco[AA * OO];
__device__ float  g_part[(ll)AA * 8 * PP * 8];        // [a][ntile][u][8]
__device__ int    g_nuniq;
__device__ int    g_ulist[PP];                        // unique row ids (sorted)
__device__ int    g_uidx [PP];                        // p -> unique index
__device__ int    g_urow [BB];                        // row -> unique index (scan)

// ---------------- helpers ----------------
__device__ __forceinline__ uint32_t smem_u32(const void* p) {
    uint32_t a;
    asm("{ .reg .u64 t; cvta.to.shared.u64 t, %1; cvt.u32.u64 %0, t; }" : "=r"(a) : "l"(p));
    return a;
}
__device__ __forceinline__ void cp16(uint32_t s, const void* g) {
    asm volatile("cp.async.cg.shared.global [%0], [%1], 16;" :: "r"(s), "l"(g));
}
__device__ __forceinline__ void cp_commit() {
    asm volatile("cp.async.commit_group;" ::: "memory");
}
template <int N>
__device__ __forceinline__ void cp_wait() {
    asm volatile("cp.async.wait_group %0;" :: "n"(N) : "memory");
}
__device__ __forceinline__ uint32_t h2u(__half2 h) {
    return *reinterpret_cast<uint32_t*>(&h);
}
__device__ __forceinline__ void mma_f16(float c[4], const uint32_t a[4], uint32_t b0, uint32_t b1) {
    asm volatile(
        "mma.sync.aligned.m16n8k16.row.col.f32.f16.f16.f32 "
        "{%0,%1,%2,%3}, {%4,%5,%6,%7}, {%8,%9}, {%0,%1,%2,%3};"
        : "+f"(c[0]), "+f"(c[1]), "+f"(c[2]), "+f"(c[3])
        : "r"(a[0]), "r"(a[1]), "r"(a[2]), "r"(a[3]), "r"(b0), "r"(b1));
}

// ---------------- dedup: unique rows of pos + inverse map ----------------
__global__ void dedup_kernel(const int* __restrict__ pos) {
    __shared__ int flag[BB];
    __shared__ int warpsum[32];
    int tid = threadIdx.x;
    for (int i = tid; i < BB; i += 1024) flag[i] = 0;
    __syncthreads();
    for (int p = tid; p < PP; p += 1024) flag[pos[p]] = 1;   // benign race, same value
    __syncthreads();
    int base = tid * 4;
    int f0 = flag[base], f1 = flag[base + 1], f2 = flag[base + 2], f3 = flag[base + 3];
    int s = f0 + f1 + f2 + f3;
    int lane = tid & 31, wid = tid >> 5;
    int ps = s;
#pragma unroll
    for (int o = 1; o < 32; o <<= 1) {
        int v = __shfl_up_sync(0xFFFFFFFFu, ps, o);
        if (lane >= o) ps += v;
    }
    if (lane == 31) warpsum[wid] = ps;
    __syncthreads();
    if (wid == 0) {
        int v = warpsum[lane];
#pragma unroll
        for (int o = 1; o < 32; o <<= 1) {
            int u2 = __shfl_up_sync(0xFFFFFFFFu, v, o);
            if (lane >= o) v += u2;
        }
        warpsum[lane] = v;
    }
    __syncthreads();
    int excl = ps - s + (wid > 0 ? warpsum[wid - 1] : 0);
    int e0 = excl, e1 = excl + f0, e2 = e1 + f1, e3 = e2 + f2;
    if (f0) g_ulist[e0] = base;
    if (f1) g_ulist[e1] = base + 1;
    if (f2) g_ulist[e2] = base + 2;
    if (f3) g_ulist[e3] = base + 3;
    g_urow[base] = e0; g_urow[base + 1] = e1; g_urow[base + 2] = e2; g_urow[base + 3] = e3;
    if (tid == 1023) g_nuniq = e3 + f3;
    __syncthreads();
    for (int p = tid; p < PP; p += 1024) g_uidx[p] = g_urow[pos[p]];
}

// ---------------- gather: unique X rows -> fp16 fragment-major A tiles ----------------
__global__ void gather_kernel(const float* __restrict__ X, const float* __restrict__ X1,
                              __half* __restrict__ Xg, __half* __restrict__ X1g) {
    __shared__ __half s0[128 * 72];
    __shared__ __half s1[128 * 72];
    int mt = blockIdx.x, kt = blockIdx.y, tid = threadIdx.x;
    int nuniq = g_nuniq;
#pragma unroll
    for (int u = 0; u < 8; ++u) {
        int idx = tid + u * 256;
        int row = idx >> 4, c4 = idx & 15;
        int uu = mt * 128 + row;
        float4 v = make_float4(0.f, 0.f, 0.f, 0.f), w = v;
        if (uu < nuniq) {
            int r = g_ulist[uu];
            v = *(const float4*)(X  + (ll)r * HH + kt * 64 + c4 * 4);
            w = *(const float4*)(X1 + (ll)r * HH + kt * 64 + c4 * 4);
        }
        *(__half2*)&s0[row * 72 + c4 * 4]     = __floats2half2_rn(v.x, v.y);
        *(__half2*)&s0[row * 72 + c4 * 4 + 2] = __floats2half2_rn(v.z, v.w);
        *(__half2*)&s1[row * 72 + c4 * 4]     = __floats2half2_rn(w.x, w.y);
        *(__half2*)&s1[row * 72 + c4 * 4 + 2] = __floats2half2_rn(w.z, w.w);
    }
    __syncthreads();
    uint4* o0 = (uint4*)(Xg  + (ll)(mt * 16 + kt) * THALF);
    uint4* o1 = (uint4*)(X1g + (ll)(mt * 16 + kt) * THALF);
#pragma unroll
    for (int c = 0; c < 4; ++c) {
        int chunk = tid + c * 256;
        int pm2 = chunk >> 9, pi = (chunk >> 7) & 3, pks = (chunk >> 5) & 3, pl = chunk & 31;
        int pg = pl >> 2, pt = pl & 3;
        int r0 = pm2 * 64 + pi * 16, k0 = pks * 16 + 2 * pt;
        o0[chunk] = make_uint4(h2u(*(__half2*)&s0[(r0 + pg) * 72 + k0]),
                               h2u(*(__half2*)&s0[(r0 + 8 + pg) * 72 + k0]),
                               h2u(*(__half2*)&s0[(r0 + pg) * 72 + k0 + 8]),
                               h2u(*(__half2*)&s0[(r0 + 8 + pg) * 72 + k0 + 8]));
        o1[chunk] = make_uint4(h2u(*(__half2*)&s1[(r0 + pg) * 72 + k0]),
                               h2u(*(__half2*)&s1[(r0 + 8 + pg) * 72 + k0]),
                               h2u(*(__half2*)&s1[(r0 + pg) * 72 + k0 + 8]),
                               h2u(*(__half2*)&s1[(r0 + 8 + pg) * 72 + k0 + 8]));
    }
}

// ---------------- round weights to fp16, ks-paired B tiles ----------------
__global__ void round_w_kernel(const float* __restrict__ Wa, const float* __restrict__ Wb,
                               int wbase, __half* __restrict__ Wd) {
    __shared__ __half swh[64 * 132];
    int nt = blockIdx.x, kt = blockIdx.y, wa = blockIdx.z;
    int wl = wa >> 4, a = wa & 15, tid = threadIdx.x;
    int w = wbase + wl;
    const float* src = (wl == 0 ? Wa : Wb) + (ll)a * HH * HH;
    const float4* srcq = (const float4*)(src + (ll)(kt * 64) * HH + nt * 128);
#pragma unroll
    for (int u = 0; u < 8; ++u) {
        int idx = tid + u * 256;
        int row = idx >> 5, c4 = idx & 31;
        float4 v = srcq[row * (HH / 4) + c4];
        *(__half2*)&swh[row * 132 + c4 * 4]     = __floats2half2_rn(v.x, v.y);
        *(__half2*)&swh[row * 132 + c4 * 4 + 2] = __floats2half2_rn(v.z, v.w);
    }
    __syncthreads();
    uint4* op = (uint4*)(Wd + (((ll)(w * 16 + a) * 8 + nt) * 16 + kt) * THALF);
#pragma unroll
    for (int c = 0; c < 4; ++c) {
        int chunk = tid + c * 256;
        int wn4 = chunk >> 8, j = (chunk >> 6) & 3, kp = (chunk >> 5) & 1, lane = chunk & 31;
        int g = lane >> 2, t = lane & 3;
        int n = wn4 * 32 + j * 8 + g;
        int k0 = kp * 32 + 2 * t;
        __half2 b00 = __halves2half2(swh[k0 * 132 + n],        swh[(k0 + 1) * 132 + n]);
        __half2 b01 = __halves2half2(swh[(k0 + 8) * 132 + n],  swh[(k0 + 9) * 132 + n]);
        __half2 b10 = __halves2half2(swh[(k0 + 16) * 132 + n], swh[(k0 + 17) * 132 + n]);
        __half2 b11 = __halves2half2(swh[(k0 + 24) * 132 + n], swh[(k0 + 25) * 132 + n]);
        op[chunk] = make_uint4(h2u(b00), h2u(b01), h2u(b10), h2u(b11));
    }
}

// ---------------- prep: gw = gamma*W4 ; Gco ; Bco ----------------
__global__ void prep_kernel(const float* __restrict__ gamma, const float* __restrict__ beta,
                            const float* __restrict__ W4, const float* __restrict__ b4,
                            float* __restrict__ gw, float* __restrict__ Gco, float* __restrict__ Bco) {
    __shared__ float red[8][256];
    int a = blockIdx.x, tid = threadIdx.x;
    float G[4] = {0, 0, 0, 0}, Bc[4] = {0, 0, 0, 0};
    for (int h = tid; h < HH; h += 256) {
        float g = gamma[a * HH + h], be = beta[a * HH + h];
        float4 w = *(const float4*)&W4[((ll)a * HH + h) * 4];
        float4 r = make_float4(g * w.x, g * w.y, g * w.z, g * w.w);
        *(float4*)&gw[((ll)a * HH + h) * 4] = r;
        G[0] += r.x; G[1] += r.y; G[2] += r.z; G[3] += r.w;
        Bc[0] += be * w.x; Bc[1] += be * w.y; Bc[2] += be * w.z; Bc[3] += be * w.w;
    }
#pragma unroll
    for (int j = 0; j < 4; ++j) { red[j][tid] = G[j]; red[4 + j][tid] = Bc[j]; }
    __syncthreads();
    for (int s = 128; s > 0; s >>= 1) {
        if (tid < s)
#pragma unroll
            for (int j = 0; j < 8; ++j) red[j][tid] += red[j][tid + s];
        __syncthreads();
    }
    if (tid < 4) {
        Gco[a * 4 + tid] = red[tid][0];
        Bco[a * 4 + tid] = red[4 + tid][0] + b4[a * 4 + tid];
    }
}

// ---------------- fp16 mma.sync m16n8k16 GEMM, BK=64, 3-stage cp.async ----------------
template <bool DUAL, bool REDUCE>
__global__ void __launch_bounds__(256, 2)
gemm_mma(const __half* __restrict__ A1, const __half* __restrict__ A2,
         const __half* __restrict__ B1, const __half* __restrict__ B2,
         const float* __restrict__ bias1, const float* __restrict__ bias2,
         const float* __restrict__ gw,
         __half* __restrict__ outZ, float* __restrict__ part) {
    if ((int)blockIdx.x * BM >= g_nuniq) return;   // dedup early-exit (uniform per CTA)
    extern __shared__ __half smh[];
    const int tid = threadIdx.x, lane = tid & 31, wid = tid >> 5;
    const int g = lane >> 2, t = lane & 3;
    const int wm2 = wid >> 2, wn4 = wid & 3;
    const int wm = wm2 * 64, wn = wn4 * 32;
    const int wodd = wid & 1;
    const int bx = blockIdx.x, by = blockIdx.y, a = blockIdx.z;
    const int m0 = bx * BM, n0 = by * BN;
    const int NIT = DUAL ? 32 : 16;

    uint32_t dA[NST], dB[NST];
    const uint4* A4b[NST];
    const uint4* B4b[NST];
#pragma unroll
    for (int s = 0; s < NST; ++s) {
        dA[s] = smem_u32(smh + s * THALF) + (uint32_t)tid * 16;
        dB[s] = smem_u32(smh + (NST + s) * THALF) + (uint32_t)tid * 16;
        A4b[s] = (const uint4*)(smh + s * THALF);
        B4b[s] = (const uint4*)(smh + (NST + s) * THALF);
    }

    const char* Ag0 = (const char*)((DUAL ? A1 + (ll)bx * 16 * THALF
                                          : A1 + ((ll)(a * 16 + bx)) * 16 * THALF)) + tid * 16;
    const char* Bg0 = (const char*)(B1 + ((ll)(a * 8 + by)) * 16 * THALF) + tid * 16;
    const char* Ag1 = DUAL ? (const char*)(A2 + (ll)bx * 16 * THALF) + tid * 16 : nullptr;
    const char* Bg1 = DUAL ? (const char*)(B2 + ((ll)(a * 8 + by)) * 16 * THALF) + tid * 16 : nullptr;

    float c[4][4][4];
#pragma unroll
    for (int i = 0; i < 4; ++i)
#pragma unroll
        for (int j = 0; j < 4; ++j)
#pragma unroll
            for (int q = 0; q < 4; ++q) c[i][j][q] = 0.f;

    auto load_stage = [&](int buf, int it) {
        const char* Ag = (DUAL && it >= 16) ? Ag1 + (ll)(it - 16) * THALF * 2 : Ag0 + (ll)it * THALF * 2;
        const char* Bg = (DUAL && it >= 16) ? Bg1 + (ll)(it - 16) * THALF * 2 : Bg0 + (ll)it * THALF * 2;
#pragma unroll
        for (int u = 0; u < 4; ++u) cp16(dA[buf] + u * 4096, Ag + u * 4096);
#pragma unroll
        for (int u = 0; u < 4; ++u) cp16(dB[buf] + u * 4096, Bg + u * 4096);
        cp_commit();
    };

    load_stage(0, 0);
    load_stage(1, 1);
    int buf = 0, buf2 = 2;
#pragma unroll 2
    for (int it = 0; it < NIT; ++it) {
        if (it == NIT - 1) cp_wait<0>();
        else               cp_wait<1>();
        __syncthreads();

        const uint4* A4 = A4b[buf];
        const uint4* B4 = B4b[buf];

#pragma unroll
        for (int kk = 0; kk < 2; ++kk) {
            int kp = wodd ? (1 - kk) : kk;
            uint4 bq[4];
#pragma unroll
            for (int j = 0; j < 4; ++j)
                bq[j] = B4[((wn4 * 4 + j) * 2 + kp) * 32 + lane];

#pragma unroll
            for (int h = 0; h < 2; ++h) {
                int ks = kp * 2 + h;
                uint32_t af[4][4];
#pragma unroll
                for (int i = 0; i < 4; ++i) {
                    uint4 v = A4[((wm2 * 4 + i) * 4 + ks) * 32 + lane];
                    af[i][0] = v.x; af[i][1] = v.y; af[i][2] = v.z; af[i][3] = v.w;
                }
#pragma unroll
                for (int i = 0; i < 4; ++i)
#pragma unroll
                    for (int j = 0; j < 4; ++j) {
                        uint32_t b0 = (h == 0) ? bq[j].x : bq[j].z;
                        uint32_t b1 = (h == 0) ? bq[j].y : bq[j].w;
                        mma_f16(c[i][j], af[i], b0, b1);
                    }
                if (kk == 0 && h == 0 && it + 2 < NIT) load_stage(buf2, it + 2);
            }
        }

        buf  = (buf  == NST - 1) ? 0 : buf + 1;
        buf2 = (buf2 == NST - 1) ? 0 : buf2 + 1;
    }
    __syncthreads();

    if (!REDUCE) {
        __half* Cs = smh;   // [128][136]
#pragma unroll
        for (int j = 0; j < 4; ++j) {
            int col = wn + j * 8 + t * 2;
            int gc = n0 + col;
            float bx0 = bias1[a * HH + gc]     + bias2[a * HH + gc];
            float by0 = bias1[a * HH + gc + 1] + bias2[a * HH + gc + 1];
#pragma unroll
            for (int i = 0; i < 4; ++i) {
                int r0 = wm + i * 16 + g;
                *(__half2*)&Cs[r0 * 136 + col]       = __floats2half2_rn(c[i][j][0] + bx0, c[i][j][1] + by0);
                *(__half2*)&Cs[(r0 + 8) * 136 + col] = __floats2half2_rn(c[i][j][2] + bx0, c[i][j][3] + by0);
            }
        }
        __syncthreads();
#pragma unroll
        for (int ktl = 0; ktl < 2; ++ktl) {
            uint4* op = (uint4*)(outZ + (((ll)(a * 16 + bx)) * 16 + by * 2 + ktl) * THALF);
#pragma unroll
            for (int cc = 0; cc < 4; ++cc) {
                int chunk = tid + cc * 256;
                int pm2 = chunk >> 9, pi = (chunk >> 7) & 3, pks = (chunk >> 5) & 3, pl = chunk & 31;
                int pg = pl >> 2, pt = pl & 3;
                int r0 = pm2 * 64 + pi * 16;
                int col = ktl * 64 + pks * 16 + 2 * pt;
                op[chunk] = make_uint4(h2u(*(__half2*)&Cs[(r0 + pg) * 136 + col]),
                                       h2u(*(__half2*)&Cs[(r0 + 8 + pg) * 136 + col]),
                                       h2u(*(__half2*)&Cs[(r0 + pg) * 136 + col + 8]),
                                       h2u(*(__half2*)&Cs[(r0 + 8 + pg) * 136 + col + 8]));
            }
        }
    } else {
        float* red = (float*)smh;   // [row][wn4][8]
        float bcol[4][2];
        float4 gcol[4][2];
#pragma unroll
        for (int j = 0; j < 4; ++j) {
            int col = n0 + wn + j * 8 + t * 2;
            bcol[j][0] = bias1[a * HH + col];
            bcol[j][1] = bias1[a * HH + col + 1];
            gcol[j][0] = *(const float4*)&gw[((ll)a * HH + col) * 4];
            gcol[j][1] = *(const float4*)&gw[((ll)a * HH + col + 1) * 4];
        }
#pragma unroll
        for (int i = 0; i < 4; ++i) {
#pragma unroll
            for (int gs = 0; gs < 2; ++gs) {
                float s1 = 0.f, s2 = 0.f, sx = 0.f, sy = 0.f, sz = 0.f, sw = 0.f;
#pragma unroll
                for (int j = 0; j < 4; ++j) {
                    float v0 = fmaxf(c[i][j][gs * 2]     + bcol[j][0], 0.f);
                    float v1 = fmaxf(c[i][j][gs * 2 + 1] + bcol[j][1], 0.f);
                    s1 += v0 + v1;
                    s2 += v0 * v0 + v1 * v1;
                    sx += v0 * gcol[j][0].x + v1 * gcol[j][1].x;
                    sy += v0 * gcol[j][0].y + v1 * gcol[j][1].y;
                    sz += v0 * gcol[j][0].z + v1 * gcol[j][1].z;
                    sw += v0 * gcol[j][0].w + v1 * gcol[j][1].w;
                }
#pragma unroll
                for (int o = 1; o <= 2; o <<= 1) {
                    s1 += __shfl_xor_sync(0xFFFFFFFFu, s1, o);
                    s2 += __shfl_xor_sync(0xFFFFFFFFu, s2, o);
                    sx += __shfl_xor_sync(0xFFFFFFFFu, sx, o);
                    sy += __shfl_xor_sync(0xFFFFFFFFu, sy, o);
                    sz += __shfl_xor_sync(0xFFFFFFFFu, sz, o);
                    sw += __shfl_xor_sync(0xFFFFFFFFu, sw, o);
                }
                if (t == 0) {
                    int rl = wm + i * 16 + gs * 8 + g;
                    float* rp = &red[(rl * 4 + wn4) * 8];
                    rp[0] = s1; rp[1] = s2; rp[2] = sx;
                    rp[3] = sy; rp[4] = sz; rp[5] = sw;
                }
            }
        }
        __syncthreads();
        for (int idx = tid; idx < 128 * 6; idx += 256) {
            int row = idx / 6, q = idx % 6;
            float s = red[(row * 4 + 0) * 8 + q] + red[(row * 4 + 1) * 8 + q]
                    + red[(row * 4 + 2) * 8 + q] + red[(row * 4 + 3) * 8 + q];
            part[(((ll)a * 8 + by) * PP + (m0 + row)) * 8 + q] = s;
        }
    }
}

// ---------------- final: map p -> unique row, combine partials, LN + projection ----------------
__global__ void final_kernel(const float* __restrict__ part, const float* __restrict__ Gco,
                             const float* __restrict__ Bco, float* __restrict__ out) {
    int tk = blockIdx.x * 256 + threadIdx.x;
    int p = tk >> 4, a = tk & 15;
    int u = g_uidx[p];
    float s1 = 0.f, s2 = 0.f, so[4] = {0.f, 0.f, 0.f, 0.f};
#pragma unroll
    for (int nt = 0; nt < 8; ++nt) {
        const float* q = part + (((ll)a * 8 + nt) * PP + u) * 8;
        s1 += q[0]; s2 += q[1];
        so[0] += q[2]; so[1] += q[3]; so[2] += q[4]; so[3] += q[5];
    }
    float mu  = s1 * (1.0f / HH);
    float var = s2 * (1.0f / HH) - mu * mu;
    float inv = rsqrtf(var + 1e-5f);
    float4 o;
    o.x = (so[0] - mu * Gco[a * 4 + 0]) * inv + Bco[a * 4 + 0];
    o.y = (so[1] - mu * Gco[a * 4 + 1]) * inv + Bco[a * 4 + 1];
    o.z = (so[2] - mu * Gco[a * 4 + 2]) * inv + Bco[a * 4 + 2];
    o.w = (so[3] - mu * Gco[a * 4 + 3]) * inv + Bco[a * 4 + 3];
    ((float4*)out)[tk] = o;
}

// ---------------- host ----------------
extern "C" void kernel_launch(void* const* d_in, const int* in_sizes, int n_in,
                              void* d_out, int out_size) {
    const float* X     = (const float*)d_in[0];
    const float* X1    = (const float*)d_in[1];
    const float* W1    = (const float*)d_in[2];
    const float* b1    = (const float*)d_in[3];
    const float* W2    = (const float*)d_in[4];
    const float* b2    = (const float*)d_in[5];
    const float* W3    = (const float*)d_in[6];
    const float* b3    = (const float*)d_in[7];
    const float* gamma = (const float*)d_in[8];
    const float* beta  = (const float*)d_in[9];
    const float* W4    = (const float*)d_in[10];
    const float* b4    = (const float*)d_in[11];
    const int*   pos   = (const int*)d_in[12];
    float* out = (float*)d_out;

    __half *pXg, *pX1g, *pW, *pZ;
    float *pgw, *pGco, *pBco, *ppart;
    cudaGetSymbolAddress((void**)&pXg,   g_Xg);
    cudaGetSymbolAddress((void**)&pX1g,  g_X1g);
    cudaGetSymbolAddress((void**)&pW,    g_W);
    cudaGetSymbolAddress((void**)&pZ,    g_Z);
    cudaGetSymbolAddress((void**)&pgw,   g_gw);
    cudaGetSymbolAddress((void**)&pGco,  g_Gco);
    cudaGetSymbolAddress((void**)&pBco,  g_Bco);
    cudaGetSymbolAddress((void**)&ppart, g_part);

    cudaFuncSetAttribute(gemm_mma<true,  false>, cudaFuncAttributeMaxDynamicSharedMemorySize, SMEM_BYTES);
    cudaFuncSetAttribute(gemm_mma<false, true >, cudaFuncAttributeMaxDynamicSharedMemorySize, SMEM_BYTES);

    const __half* W1r = pW;
    const __half* W2r = pW + 1ll * AA * HH * HH;
    const __half* W3r = pW + 2ll * AA * HH * HH;

    cudaStream_t s2;
    cudaStreamCreateWithFlags(&s2, cudaStreamNonBlocking);
    cudaEvent_t eFork, eG, eW3;
    cudaEventCreateWithFlags(&eFork, cudaEventDisableTiming);
    cudaEventCreateWithFlags(&eG,    cudaEventDisableTiming);
    cudaEventCreateWithFlags(&eW3,   cudaEventDisableTiming);

    cudaEventRecord(eFork, 0);
    cudaStreamWaitEvent(s2, eFork, 0);

    // s2: dedup -> gather (unique rows) -> prep
    dedup_kernel<<<1, 1024, 0, s2>>>(pos);
    gather_kernel<<<dim3(PP / BM, 16), 256, 0, s2>>>(X, X1, pXg, pX1g);
    prep_kernel<<<AA, 256, 0, s2>>>(gamma, beta, W4, b4, pgw, pGco, pBco);
    cudaEventRecord(eG, s2);

    // s0: round W1,W2 concurrent with dedup/gather/prep
    round_w_kernel<<<dim3(8, 16, 32), 256>>>(W1, W2, 0, pW);

    // s2: round W3 concurrent with GEMM1
    round_w_kernel<<<dim3(8, 16, 16), 256, 0, s2>>>(W3, W3, 2, pW);
    cudaEventRecord(eW3, s2);

    cudaStreamWaitEvent(0, eG, 0);
    dim3 gg(PP / BM, HH / BN, AA);
    gemm_mma<true, false><<<gg, 256, SMEM_BYTES>>>(
        pXg, pX1g, W1r, W2r, b1, b2, nullptr, pZ, nullptr);

    cudaStreamWaitEvent(0, eW3, 0);
    gemm_mma<false, true><<<gg, 256, SMEM_BYTES>>>(
        pZ, nullptr, W3r, nullptr, b3, nullptr, pgw, nullptr, ppart);
    final_kernel<<<(PP * AA) / 256, 256>>>(ppart, pGco, pBco, out);
}